// round 15
// baseline (speedup 1.0000x reference)
#include <cuda_runtime.h>
#include <cuda_bf16.h>
#include <cuda_fp16.h>
#include <cstdint>

#define NPTS 120000
#define NBLK96 1250   // 120000 / 96 exactly
#define NBLK192 625   // 120000 / 192 exactly

// ---------------- scratch (device globals: allocation-free) ----------------
__device__ __half g_Ah[NPTS * 128];                 // branch a residual (fp16)
__device__ __half g_Bh[NPTS * 128];                 // branch b residual (fp16)
__device__ __half g_T2a[NPTS * 64];                 // conv output (fp16), branch a
__device__ __half g_T2b[NPTS * 64];
__device__ __half g_T16a[NPTS * 64];                // conv input (fp16), branch a
__device__ __half g_T16b[NPTS * 64];
__device__ __half g_WtH[6 * 27 * 64 * 64];          // conv weights [u][k][j][c] fp16
__device__ __half g_V1H[6 * 64 * 128];              // down weights [u][n][k] fp16 hi/lo
__device__ __half g_V1L[6 * 64 * 128];
__device__ __half g_V1cH[128 * 128];                // concat down weights units 0|3
__device__ __half g_V1cL[128 * 128];
__device__ __half g_V2H[6 * 128 * 64];              // up weights [u][n][k] fp16 hi/lo
__device__ __half g_V2L[6 * 128 * 64];
__device__ __half g_VfH[128 * 128];                 // final weights [n][k] fp16 hi/lo
__device__ __half g_VfL[128 * 128];

// ---------------- helpers ---------------------------------------------------
__device__ __forceinline__ uint32_t smem_u32(const void* p) {
    uint32_t a;
    asm("{ .reg .u64 t; cvta.to.shared.u64 t, %1; cvt.u32.u64 %0, t; }"
        : "=r"(a) : "l"(p));
    return a;
}
__device__ __forceinline__ void ldsm_x4(uint32_t (&r)[4], uint32_t addr) {
    asm volatile("ldmatrix.sync.aligned.m8n8.x4.shared.b16 {%0,%1,%2,%3}, [%4];"
                 : "=r"(r[0]), "=r"(r[1]), "=r"(r[2]), "=r"(r[3]) : "r"(addr));
}
__device__ __forceinline__ void ldsm_x2(uint32_t (&r)[2], uint32_t addr) {
    asm volatile("ldmatrix.sync.aligned.m8n8.x2.shared.b16 {%0,%1}, [%2];"
                 : "=r"(r[0]), "=r"(r[1]) : "r"(addr));
}
__device__ __forceinline__ void mma_f16(float* c, const uint32_t* a,
                                        uint32_t b0, uint32_t b1) {
    asm volatile(
        "mma.sync.aligned.m16n8k16.row.col.f32.f16.f16.f32 "
        "{%0,%1,%2,%3}, {%4,%5,%6,%7}, {%8,%9}, {%0,%1,%2,%3};"
        : "+f"(c[0]), "+f"(c[1]), "+f"(c[2]), "+f"(c[3])
        : "r"(a[0]), "r"(a[1]), "r"(a[2]), "r"(a[3]), "r"(b0), "r"(b1));
}
__device__ __forceinline__ void cp_async16(uint32_t dst, const void* src,
                                           uint32_t src_size) {
    asm volatile("cp.async.ca.shared.global [%0], [%1], 16, %2;"
                 :: "r"(dst), "l"(src), "r"(src_size) : "memory");
}
__device__ __forceinline__ void cp_commit() {
    asm volatile("cp.async.commit_group;" ::: "memory");
}
template <int N>
__device__ __forceinline__ void cp_wait() {
    asm volatile("cp.async.wait_group %0;" :: "n"(N) : "memory");
}
__device__ __forceinline__ unsigned h2u(__half2 h) {
    return *reinterpret_cast<unsigned*>(&h);
}
__device__ __forceinline__ float2 h2f2(__half2 h) {
    return __half22float2(h);
}

// ---------------------------------------------------------------------------
// conv weight transpose: Wt[u][k][j][c] = Wk[u][k][c][j] as single fp16
// ---------------------------------------------------------------------------
__global__ void k_wsplit(const float* __restrict__ Wks,
                         __half* __restrict__ WtH) {
    int k = blockIdx.x, u = blockIdx.y;
    const float* src = Wks + ((size_t)u * 27 + k) * 4096;
    __half* dh = WtH + ((size_t)u * 27 + k) * 4096;
    for (int e = threadIdx.x; e < 4096; e += blockDim.x) {
        int c = e >> 6, j = e & 63;
        dh[j * 64 + c] = __float2half(src[c * 64 + j]);
    }
}

// ---------------------------------------------------------------------------
// linear weight split+transpose: [k][n] fp32 -> [n][k] fp16 hi/lo
// blocks 0-5: W1 units; 6-11: W2 units; 12: Wf; 13: concat W1 units 0|3
// ---------------------------------------------------------------------------
__global__ void k_wsplit_lin(const float* __restrict__ W1s,
                             const float* __restrict__ W2s,
                             const float* __restrict__ Wf,
                             __half* __restrict__ V1H, __half* __restrict__ V1L,
                             __half* __restrict__ V1cH, __half* __restrict__ V1cL,
                             __half* __restrict__ V2H, __half* __restrict__ V2L,
                             __half* __restrict__ VfH, __half* __restrict__ VfL) {
    int b = blockIdx.x;
    if (b < 6) {
        const float* s = W1s + (size_t)b * 8192;
        __half* vh = V1H + (size_t)b * 8192;
        __half* vl = V1L + (size_t)b * 8192;
        for (int e = threadIdx.x; e < 8192; e += blockDim.x) {
            int k = e >> 6, n = e & 63;
            float v = s[e];
            __half fh = __float2half(v);
            vh[n * 128 + k] = fh;
            vl[n * 128 + k] = __float2half(v - __half2float(fh));
        }
    } else if (b < 12) {
        const float* s = W2s + (size_t)(b - 6) * 8192;
        __half* vh = V2H + (size_t)(b - 6) * 8192;
        __half* vl = V2L + (size_t)(b - 6) * 8192;
        for (int e = threadIdx.x; e < 8192; e += blockDim.x) {
            int k = e >> 7, n = e & 127;
            float v = s[e];
            __half fh = __float2half(v);
            vh[n * 64 + k] = fh;
            vl[n * 64 + k] = __float2half(v - __half2float(fh));
        }
    } else if (b == 12) {
        for (int e = threadIdx.x; e < 16384; e += blockDim.x) {
            int k = e >> 7, n = e & 127;
            float v = Wf[e];
            __half fh = __float2half(v);
            VfH[n * 128 + k] = fh;
            VfL[n * 128 + k] = __float2half(v - __half2float(fh));
        }
    } else {
        // concat: rows 0-63 = unit0, rows 64-127 = unit3
        for (int e = threadIdx.x; e < 16384; e += blockDim.x) {
            int k = e >> 7, n = e & 127;
            int u = (n < 64) ? 0 : 3;
            float v = W1s[(size_t)u * 8192 + k * 64 + (n & 63)];
            __half fh = __float2half(v);
            V1cH[n * 128 + k] = fh;
            V1cL[n * 128 + k] = __float2half(v - __half2float(fh));
        }
    }
}

// ---------------------------------------------------------------------------
// HMMA 1x1 layer, M=96 tiles, fp16 2-product, DUAL-BRANCH:
// EPI 1: in16 fp16 -> relu(acc+res) -> fp16 residual out (stride 128) [up]
//        res = resh (fp16) if RESH else resf (fp32)
// EPI 2: in16 fp16 (stride 128) -> resh*sigmoid(acc)+xres -> fp32     [final]
// EPI 3: in fp32 -> relu -> fp16, cols 0-63 -> out16_a, 64-127 -> out16_b
//        (single-branch grid NBLK96)                                   [down]
// ---------------------------------------------------------------------------
template <int K, int N, int EPI, int RESH>
__global__ __launch_bounds__(256, 2) void k_lin(
    const float* in_a, const __half* in16_a,
    const __half* BHa, const __half* BLa,
    const __half* resh_a, const float* resf_a, const float* xres_a,
    float* fout_a, __half* out16_a,
    const float* in_b, const __half* in16_b,
    const __half* BHb, const __half* BLb,
    const __half* resh_b, const float* resf_b, const float* xres_b,
    float* fout_b, __half* out16_b)
{
    constexpr int SB   = K * 2 + 16;
    constexpr int BOFF = 96 * SB;
    constexpr int NTW  = N / 4;
    constexpr int NT   = NTW / 8;
    constexpr int KS   = K / 16;

    extern __shared__ char sm[];
    const uint32_t su = smem_u32(sm);
    const int tid  = threadIdx.x;
    const int lane = tid & 31;
    const int w    = tid >> 5;
    const int wm   = w & 1;
    const int wn   = w >> 1;
    const int mbase = wm * 48;

    const int bid = blockIdx.x;
    const bool sel = bid >= NBLK96;
    const int p0 = (sel ? bid - NBLK96 : bid) * 96;
    const float*  in    = sel ? in_b    : in_a;
    const __half* in16  = sel ? in16_b  : in16_a;
    const __half* BH    = sel ? BHb     : BHa;
    const __half* BL    = sel ? BLb     : BLa;
    const __half* resh  = sel ? resh_b  : resh_a;
    const float*  resf  = sel ? resf_b  : resf_a;
    const float*  xres  = sel ? xres_b  : xres_a;
    float*        fout  = sel ? fout_b  : fout_a;
    __half*       out16 = sel ? out16_b : out16_a;

    // ---- stage A ----
    if (EPI == 1 || EPI == 2) {
        constexpr int CH = 96 * K / 8;
#pragma unroll
        for (int i = 0; i < CH / 256; i++) {
            int j = tid + i * 256;
            int row = j / (K / 8), ch = j % (K / 8);
            *(uint4*)(sm + row * SB + ch * 16) =
                *(const uint4*)(in16 + (size_t)(p0 + row) * K + ch * 8);
        }
    } else {
        constexpr int UNITS = 96 * K / 8;
#pragma unroll
        for (int i = 0; i < UNITS / 256; i++) {
            int j = tid + i * 256;
            int row = j / (K / 8), q = j % (K / 8);
            const float* src = in + (size_t)(p0 + row) * K + q * 8;
            float4 f0 = *(const float4*)(src);
            float4 f1 = *(const float4*)(src + 4);
            *(uint4*)(sm + row * SB + q * 16) = make_uint4(
                h2u(__floats2half2_rn(f0.x, f0.y)),
                h2u(__floats2half2_rn(f0.z, f0.w)),
                h2u(__floats2half2_rn(f1.x, f1.y)),
                h2u(__floats2half2_rn(f1.z, f1.w)));
        }
    }
    // ---- stage B (fp16 hi/lo) ----
    {
        constexpr int ITER = N * K / 1024;
        int plane = tid >> 7, t = tid & 127;
        const __half* bs = plane ? BL : BH;
        char* bd = sm + BOFF + plane * (N * SB);
#pragma unroll
        for (int i = 0; i < ITER; i++) {
            int j = t + i * 128;
            int e = j * 8;
            int r = e / K, c = e % K;
            *(uint4*)(bd + r * SB + c * 2) = *(const uint4*)(bs + e);
        }
    }
    __syncthreads();

    float acc[3][NT][4];
#pragma unroll
    for (int mt = 0; mt < 3; mt++)
#pragma unroll
        for (int nt = 0; nt < NT; nt++)
#pragma unroll
            for (int e = 0; e < 4; e++) acc[mt][nt][e] = 0.f;

    const uint32_t a_ld = su + (uint32_t)(mbase + (lane & 15)) * SB
                        + (uint32_t)(lane >> 4) * 16;
    const uint32_t b_ld = su + BOFF + (uint32_t)(wn * NTW + (lane & 7)) * SB
                        + (uint32_t)((lane >> 3) & 1) * 16;

#pragma unroll
    for (int ks = 0; ks < KS; ks++) {
        uint32_t a[3][4];
#pragma unroll
        for (int mt = 0; mt < 3; mt++)
            ldsm_x4(a[mt], a_ld + (uint32_t)mt * (16 * SB) + ks * 32);
#pragma unroll
        for (int nt = 0; nt < NT; nt++) {
            uint32_t bh[2], bl[2];
            ldsm_x2(bh, b_ld + (uint32_t)nt * (8 * SB) + ks * 32);
            ldsm_x2(bl, b_ld + (uint32_t)(N * SB) + (uint32_t)nt * (8 * SB) + ks * 32);
#pragma unroll
            for (int mt = 0; mt < 3; mt++) {
                mma_f16(acc[mt][nt], a[mt], bh[0], bh[1]);
                mma_f16(acc[mt][nt], a[mt], bl[0], bl[1]);
            }
        }
    }

    const int g = lane >> 2, tg = lane & 3;
#pragma unroll
    for (int mt = 0; mt < 3; mt++) {
        int r0 = p0 + mbase + mt * 16 + g;
#pragma unroll
        for (int nt = 0; nt < NT; nt++) {
            int col = wn * NTW + nt * 8 + tg * 2;
            float c0 = acc[mt][nt][0], c1 = acc[mt][nt][1];
            float c2 = acc[mt][nt][2], c3 = acc[mt][nt][3];
            if (EPI == 3) {
                __half* d0 = (col < 64) ? out16_a : out16_b;
                int cc = col & 63;
                *(__half2*)(d0 + (size_t)r0 * 64 + cc) =
                    __floats2half2_rn(fmaxf(c0, 0.f), fmaxf(c1, 0.f));
                *(__half2*)(d0 + (size_t)(r0 + 8) * 64 + cc) =
                    __floats2half2_rn(fmaxf(c2, 0.f), fmaxf(c3, 0.f));
            } else if (EPI == 1) {
                float2 ra, rb;
                if (RESH) {
                    ra = h2f2(*(const __half2*)(resh + (size_t)r0 * 128 + col));
                    rb = h2f2(*(const __half2*)(resh + (size_t)(r0 + 8) * 128 + col));
                } else {
                    ra = *(const float2*)(resf + (size_t)r0 * 128 + col);
                    rb = *(const float2*)(resf + (size_t)(r0 + 8) * 128 + col);
                }
                *(__half2*)(out16 + (size_t)r0 * 128 + col) =
                    __floats2half2_rn(fmaxf(c0 + ra.x, 0.f), fmaxf(c1 + ra.y, 0.f));
                *(__half2*)(out16 + (size_t)(r0 + 8) * 128 + col) =
                    __floats2half2_rn(fmaxf(c2 + rb.x, 0.f), fmaxf(c3 + rb.y, 0.f));
            } else {  // EPI == 2
                float2 aa = h2f2(*(const __half2*)(resh + (size_t)r0 * 128 + col));
                float2 ab = h2f2(*(const __half2*)(resh + (size_t)(r0 + 8) * 128 + col));
                float2 xa = *(const float2*)(xres + (size_t)r0 * 128 + col);
                float2 xb = *(const float2*)(xres + (size_t)(r0 + 8) * 128 + col);
                float2 o0, o1;
                o0.x = aa.x / (1.f + __expf(-c0)) + xa.x;
                o0.y = aa.y / (1.f + __expf(-c1)) + xa.y;
                o1.x = ab.x / (1.f + __expf(-c2)) + xb.x;
                o1.y = ab.y / (1.f + __expf(-c3)) + xb.y;
                *(float2*)(fout + (size_t)r0 * 128 + col) = o0;
                *(float2*)(fout + (size_t)(r0 + 8) * 128 + col) = o1;
            }
        }
    }
}

// ---------------------------------------------------------------------------
// FUSED up_i + down_{i+1}, M=96, fp16 2-product, DUAL-BRANCH.
// RESH: residual source fp16 (1) or fp32 (0). Residual OUT is fp16 (stride 128).
// ---------------------------------------------------------------------------
#define UD_SB1 144
#define UD_B1 26112
#define UD_SB2 272
#define UD_B2 62976
#define UD_SMEM 97792

template <int RESH>
__global__ __launch_bounds__(256, 2) void k_updown(
    const __half* t2_a, const __half* W2Ha, const __half* W2La,
    const __half* resh_a, const float* resf_a, __half* hout_a,
    const __half* V1Ha, const __half* V1La, __half* out16_a,
    const __half* t2_b, const __half* W2Hb, const __half* W2Lb,
    const __half* resh_b, const float* resf_b, __half* hout_b,
    const __half* V1Hb, const __half* V1Lb, __half* out16_b)
{
    extern __shared__ char sm[];
    const uint32_t su = smem_u32(sm);
    const int tid  = threadIdx.x;
    const int lane = tid & 31;
    const int w    = tid >> 5;
    const int wm   = w & 1;
    const int wn   = w >> 1;
    const int mbase = wm * 48;

    const int bid = blockIdx.x;
    const bool sel = bid >= NBLK96;
    const int p0 = (sel ? bid - NBLK96 : bid) * 96;
    const __half* t2h   = sel ? t2_b    : t2_a;
    const __half* W2Hp  = sel ? W2Hb    : W2Ha;
    const __half* W2Lp  = sel ? W2Lb    : W2La;
    const __half* resh  = sel ? resh_b  : resh_a;
    const float*  resf  = sel ? resf_b  : resf_a;
    __half*       hout  = sel ? hout_b  : hout_a;
    const __half* V1Hp  = sel ? V1Hb    : V1Ha;
    const __half* V1Lp  = sel ? V1Lb    : V1La;
    __half*       out16 = sel ? out16_b : out16_a;

#pragma unroll
    for (int i = 0; i < 3; i++) {
        int j = tid + i * 256;
        int row = j >> 3, ch = j & 7;
        *(uint4*)(sm + row * UD_SB1 + ch * 16) =
            *(const uint4*)(t2h + (size_t)(p0 + row) * 64 + ch * 8);
    }
    {
        int plane = tid >> 7, t = tid & 127;
        const __half* bs = plane ? W2Lp : W2Hp;
        char* bd = sm + UD_B1 + plane * 18432;
#pragma unroll
        for (int i = 0; i < 8; i++) {
            int j = t + i * 128;
            int e = j * 8;
            int r = e >> 6, c = e & 63;
            *(uint4*)(bd + r * UD_SB1 + c * 2) = *(const uint4*)(bs + e);
        }
    }
    {
        int plane = tid >> 7, t = tid & 127;
        const __half* bs = plane ? V1Lp : V1Hp;
        char* bd = sm + UD_B2 + plane * 17408;
#pragma unroll
        for (int i = 0; i < 8; i++) {
            int j = t + i * 128;
            int e = j * 8;
            int r = e >> 7, c = e & 127;
            *(uint4*)(bd + r * UD_SB2 + c * 2) = *(const uint4*)(bs + e);
        }
    }
    __syncthreads();

    float acc[3][4][4];
#pragma unroll
    for (int mt = 0; mt < 3; mt++)
#pragma unroll
        for (int nt = 0; nt < 4; nt++)
#pragma unroll
            for (int e = 0; e < 4; e++) acc[mt][nt][e] = 0.f;

    {
        const uint32_t a_ld = su + (uint32_t)(mbase + (lane & 15)) * UD_SB1
                            + (uint32_t)(lane >> 4) * 16;
        const uint32_t b_ld = su + UD_B1 + (uint32_t)(wn * 32 + (lane & 7)) * UD_SB1
                            + (uint32_t)((lane >> 3) & 1) * 16;
#pragma unroll
        for (int ks = 0; ks < 4; ks++) {
            uint32_t a[3][4];
#pragma unroll
            for (int mt = 0; mt < 3; mt++)
                ldsm_x4(a[mt], a_ld + (uint32_t)mt * (16 * UD_SB1) + ks * 32);
#pragma unroll
            for (int nt = 0; nt < 4; nt++) {
                uint32_t bh[2], bl[2];
                ldsm_x2(bh, b_ld + (uint32_t)nt * (8 * UD_SB1) + ks * 32);
                ldsm_x2(bl, b_ld + 18432u + (uint32_t)nt * (8 * UD_SB1) + ks * 32);
#pragma unroll
                for (int mt = 0; mt < 3; mt++) {
                    mma_f16(acc[mt][nt], a[mt], bh[0], bh[1]);
                    mma_f16(acc[mt][nt], a[mt], bl[0], bl[1]);
                }
            }
        }
    }
    __syncthreads();

    const int g = lane >> 2, tg = lane & 3;
#pragma unroll
    for (int mt = 0; mt < 3; mt++) {
        int lr0 = mbase + mt * 16 + g;
        int r0 = p0 + lr0;
#pragma unroll
        for (int nt = 0; nt < 4; nt++) {
            int col = wn * 32 + nt * 8 + tg * 2;
            float2 ra, rb;
            if (RESH) {
                ra = h2f2(*(const __half2*)(resh + (size_t)r0 * 128 + col));
                rb = h2f2(*(const __half2*)(resh + (size_t)(r0 + 8) * 128 + col));
            } else {
                ra = *(const float2*)(resf + (size_t)r0 * 128 + col);
                rb = *(const float2*)(resf + (size_t)(r0 + 8) * 128 + col);
            }
            __half2 o0 = __floats2half2_rn(fmaxf(acc[mt][nt][0] + ra.x, 0.f),
                                           fmaxf(acc[mt][nt][1] + ra.y, 0.f));
            __half2 o1 = __floats2half2_rn(fmaxf(acc[mt][nt][2] + rb.x, 0.f),
                                           fmaxf(acc[mt][nt][3] + rb.y, 0.f));
            *(__half2*)(hout + (size_t)r0 * 128 + col) = o0;
            *(__half2*)(hout + (size_t)(r0 + 8) * 128 + col) = o1;
            *(__half2*)(sm + lr0 * UD_SB2 + col * 2) = o0;
            *(__half2*)(sm + (lr0 + 8) * UD_SB2 + col * 2) = o1;
        }
    }
    __syncthreads();

    float acc2[3][2][4];
#pragma unroll
    for (int mt = 0; mt < 3; mt++)
#pragma unroll
        for (int nt = 0; nt < 2; nt++)
#pragma unroll
            for (int e = 0; e < 4; e++) acc2[mt][nt][e] = 0.f;

    {
        const uint32_t a_ld = su + (uint32_t)(mbase + (lane & 15)) * UD_SB2
                            + (uint32_t)(lane >> 4) * 16;
        const uint32_t b_ld = su + UD_B2 + (uint32_t)(wn * 16 + (lane & 7)) * UD_SB2
                            + (uint32_t)((lane >> 3) & 1) * 16;
#pragma unroll
        for (int ks = 0; ks < 8; ks++) {
            uint32_t a[3][4];
#pragma unroll
            for (int mt = 0; mt < 3; mt++)
                ldsm_x4(a[mt], a_ld + (uint32_t)mt * (16 * UD_SB2) + ks * 32);
#pragma unroll
            for (int nt = 0; nt < 2; nt++) {
                uint32_t bh[2], bl[2];
                ldsm_x2(bh, b_ld + (uint32_t)nt * (8 * UD_SB2) + ks * 32);
                ldsm_x2(bl, b_ld + 17408u + (uint32_t)nt * (8 * UD_SB2) + ks * 32);
#pragma unroll
                for (int mt = 0; mt < 3; mt++) {
                    mma_f16(acc2[mt][nt], a[mt], bh[0], bh[1]);
                    mma_f16(acc2[mt][nt], a[mt], bl[0], bl[1]);
                }
            }
        }
    }

#pragma unroll
    for (int mt = 0; mt < 3; mt++) {
        int r0 = p0 + mbase + mt * 16 + g;
#pragma unroll
        for (int nt = 0; nt < 2; nt++) {
            int col = wn * 16 + nt * 8 + tg * 2;
            __half2 o0 = __floats2half2_rn(fmaxf(acc2[mt][nt][0], 0.f),
                                           fmaxf(acc2[mt][nt][1], 0.f));
            __half2 o1 = __floats2half2_rn(fmaxf(acc2[mt][nt][2], 0.f),
                                           fmaxf(acc2[mt][nt][3], 0.f));
            *(__half2*)(out16 + (size_t)r0 * 64 + col) = o0;
            *(__half2*)(out16 + (size_t)(r0 + 8) * 64 + col) = o1;
        }
    }
}

// ---------------------------------------------------------------------------
// fp16 HMMA conv, DUAL-BRANCH, 2-stage cp.async, smem idx (round-13 proven)
// ---------------------------------------------------------------------------
#define ASTRIDE 144
#define STAGE_SZ 36864
#define SB_B 27648
#define IDX_OFF 73728
#define CONV_SMEM (IDX_OFF + 20736)

__global__ __launch_bounds__(256, 2) void k_conv_mma(
    const __half* T16a, const __half* Wta, __half* outa,
    const __half* T16b, const __half* Wtb, __half* outb,
    const int* __restrict__ nbr)
{
    extern __shared__ char sm[];
    const int tid  = threadIdx.x;
    const int lane = tid & 31;
    const int w    = tid >> 5;
    const int wm   = w & 3;
    const int wn   = w >> 2;

    const int bid = blockIdx.x;
    const bool selb = bid >= NBLK192;
    const int p0 = (selb ? bid - NBLK192 : bid) * 192;
    const __half* T16  = selb ? T16b : T16a;
    const __half* WtH  = selb ? Wtb  : Wta;
    __half*       outh = selb ? outb : outa;

    const uint32_t su = smem_u32(sm);
    int* idxs = (int*)(sm + IDX_OFF);

    for (int i = tid; i < 27 * 192; i += 256) {
        int p = i / 27;
        int k = i - p * 27;
        idxs[k * 192 + p] = nbr[(size_t)(p0 + p) * 27 + k];
    }

    float acc[3][4][4];
#pragma unroll
    for (int mt = 0; mt < 3; mt++)
#pragma unroll
        for (int nt = 0; nt < 4; nt++)
#pragma unroll
            for (int e = 0; e < 4; e++) acc[mt][nt][e] = 0.f;

    const uint32_t a_ld0 = su + (uint32_t)(wm * 48 + (lane & 15)) * ASTRIDE
                         + (uint32_t)(lane >> 4) * 16;
    const uint32_t b_ld0 = su + SB_B + (uint32_t)(wn * 32 + (lane & 15)) * ASTRIDE
                         + (uint32_t)(lane >> 4) * 16;

    __syncthreads();

    auto issue_tap = [&](int k, uint32_t sbase) {
#pragma unroll
        for (int i = 0; i < 6; i++) {
            int j = tid + i * 256;
            int row = j >> 3, ch = j & 7;
            int gr = idxs[k * 192 + row];
            uint32_t dst = sbase + (uint32_t)row * ASTRIDE + (uint32_t)ch * 16;
            const void* src = T16 + ((size_t)(gr < 0 ? 0 : gr) * 64 + ch * 8);
            cp_async16(dst, src, gr < 0 ? 0u : 16u);
        }
#pragma unroll
        for (int i = 0; i < 2; i++) {
            int j = tid + i * 256;
            int row = j >> 3, ch = j & 7;
            uint32_t dst = sbase + (uint32_t)SB_B
                         + (uint32_t)row * ASTRIDE + (uint32_t)ch * 16;
            const __half* src = WtH + ((size_t)k * 64 + row) * 64 + ch * 8;
            cp_async16(dst, src, 16u);
        }
        cp_commit();
    };

    issue_tap(0, su);
    issue_tap(1, su + STAGE_SZ);

    for (int k = 0; k < 27; k++) {
        const uint32_t sb = (uint32_t)(k & 1) * STAGE_SZ;
        if (k < 26) cp_wait<1>(); else cp_wait<0>();
        __syncthreads();

        const uint32_t a_ld = a_ld0 + sb;
        const uint32_t b_ld = b_ld0 + sb;
#pragma unroll
        for (int ks = 0; ks < 4; ks++) {
            uint32_t a[3][4];
#pragma unroll
            for (int mt = 0; mt < 3; mt++)
                ldsm_x4(a[mt], a_ld + (uint32_t)mt * (16 * ASTRIDE) + ks * 32);
#pragma unroll
            for (int nt2 = 0; nt2 < 2; nt2++) {
                uint32_t bh[4];
                ldsm_x4(bh, b_ld + (uint32_t)nt2 * (16 * ASTRIDE) + ks * 32);
#pragma unroll
                for (int mt = 0; mt < 3; mt++) {
                    mma_f16(acc[mt][nt2 * 2 + 0], a[mt], bh[0], bh[2]);
                    mma_f16(acc[mt][nt2 * 2 + 1], a[mt], bh[1], bh[3]);
                }
            }
        }

        if (k < 25) {
            __syncthreads();
            issue_tap(k + 2, su + sb);
        }
    }

    const int g = lane >> 2, tg = lane & 3;
#pragma unroll
    for (int mt = 0; mt < 3; mt++) {
        int row0 = p0 + wm * 48 + mt * 16 + g;
#pragma unroll
        for (int nt = 0; nt < 4; nt++) {
            int col = wn * 32 + nt * 8 + tg * 2;
            __half2 o0 = __floats2half2_rn(fmaxf(acc[mt][nt][0], 0.f),
                                           fmaxf(acc[mt][nt][1], 0.f));
            __half2 o1 = __floats2half2_rn(fmaxf(acc[mt][nt][2], 0.f),
                                           fmaxf(acc[mt][nt][3], 0.f));
            *(__half2*)(outh + (size_t)row0 * 64 + col) = o0;
            *(__half2*)(outh + (size_t)(row0 + 8) * 64 + col) = o1;
        }
    }
}

// ---------------------------------------------------------------------------
extern "C" void kernel_launch(void* const* d_in, const int* in_sizes, int n_in,
                              void* d_out, int out_size)
{
    const float* x   = (const float*)d_in[0];
    const float* W1s = (const float*)d_in[1];
    const float* Wks = (const float*)d_in[2];
    const float* W2s = (const float*)d_in[3];
    const float* Wf  = (const float*)d_in[4];
    const int*   nbr = (const int*)d_in[5];
    float* out = (float*)d_out;

    __half *Ah, *Bh, *T2a, *T2b, *T16a, *T16b, *WtH;
    __half *V1H, *V1L, *V1cH, *V1cL, *V2H, *V2L, *VfH, *VfL;
    cudaGetSymbolAddress((void**)&Ah,   g_Ah);
    cudaGetSymbolAddress((void**)&Bh,   g_Bh);
    cudaGetSymbolAddress((void**)&T2a,  g_T2a);
    cudaGetSymbolAddress((void**)&T2b,  g_T2b);
    cudaGetSymbolAddress((void**)&T16a, g_T16a);
    cudaGetSymbolAddress((void**)&T16b, g_T16b);
    cudaGetSymbolAddress((void**)&WtH,  g_WtH);
    cudaGetSymbolAddress((void**)&V1H,  g_V1H);
    cudaGetSymbolAddress((void**)&V1L,  g_V1L);
    cudaGetSymbolAddress((void**)&V1cH, g_V1cH);
    cudaGetSymbolAddress((void**)&V1cL, g_V1cL);
    cudaGetSymbolAddress((void**)&V2H,  g_V2H);
    cudaGetSymbolAddress((void**)&V2L,  g_V2L);
    cudaGetSymbolAddress((void**)&VfH,  g_VfH);
    cudaGetSymbolAddress((void**)&VfL,  g_VfL);

    constexpr int SM_DOWN  = 96 * 272 + 2 * 128 * 272;   // 95744
    constexpr int SM_UP    = 96 * 144 + 2 * 128 * 144;   // 50688
    constexpr int SM_FINAL = 96 * 272 + 2 * 128 * 272;   // 95744

    cudaFuncSetAttribute(k_conv_mma, cudaFuncAttributeMaxDynamicSharedMemorySize,
                         CONV_SMEM);
    cudaFuncSetAttribute((const void*)k_updown<0>,
                         cudaFuncAttributeMaxDynamicSharedMemorySize, UD_SMEM);
    cudaFuncSetAttribute((const void*)k_updown<1>,
                         cudaFuncAttributeMaxDynamicSharedMemorySize, UD_SMEM);
    cudaFuncSetAttribute((const void*)k_lin<128, 128, 3, 0>,
                         cudaFuncAttributeMaxDynamicSharedMemorySize, SM_DOWN);
    cudaFuncSetAttribute((const void*)k_lin<64, 128, 1, 1>,
                         cudaFuncAttributeMaxDynamicSharedMemorySize, SM_UP);
    cudaFuncSetAttribute((const void*)k_lin<128, 128, 2, 1>,
                         cudaFuncAttributeMaxDynamicSharedMemorySize, SM_FINAL);

    k_wsplit<<<dim3(27, 6), 256>>>(Wks, WtH);
    k_wsplit_lin<<<14, 256>>>(W1s, W2s, Wf, V1H, V1L, V1cH, V1cL,
                              V2H, V2L, VfH, VfL);

    // single-pass down: x @ [W1_0 | W1_3] -> T16a (cols 0-63), T16b (64-127)
    k_lin<128, 128, 3, 0><<<NBLK96, 256, SM_DOWN>>>(
        x, nullptr, V1cH, V1cL, nullptr, nullptr, nullptr, nullptr, T16a,
        x, nullptr, V1cH, V1cL, nullptr, nullptr, nullptr, nullptr, T16b);

    // step 0: conv + updown (residual = x fp32 -> h fp16)
    k_conv_mma<<<2 * NBLK192, 256, CONV_SMEM>>>(
        T16a, WtH, T2a, T16b, WtH + (size_t)3 * 27 * 4096, T2b, nbr);
    k_updown<0><<<2 * NBLK96, 256, UD_SMEM>>>(
        T2a, V2H, V2L, nullptr, x, Ah, V1H + (size_t)1 * 8192,
        V1L + (size_t)1 * 8192, T16a,
        T2b, V2H + (size_t)3 * 8192, V2L + (size_t)3 * 8192, nullptr, x, Bh,
        V1H + (size_t)4 * 8192, V1L + (size_t)4 * 8192, T16b);

    // step 1: conv + updown (residual fp16 in/out)
    k_conv_mma<<<2 * NBLK192, 256, CONV_SMEM>>>(
        T16a, WtH + (size_t)1 * 27 * 4096, T2a,
        T16b, WtH + (size_t)4 * 27 * 4096, T2b, nbr);
    k_updown<1><<<2 * NBLK96, 256, UD_SMEM>>>(
        T2a, V2H + (size_t)1 * 8192, V2L + (size_t)1 * 8192, Ah, nullptr, Ah,
        V1H + (size_t)2 * 8192, V1L + (size_t)2 * 8192, T16a,
        T2b, V2H + (size_t)4 * 8192, V2L + (size_t)4 * 8192, Bh, nullptr, Bh,
        V1H + (size_t)5 * 8192, V1L + (size_t)5 * 8192, T16b);

    // last conv (units 2 and 5)
    k_conv_mma<<<2 * NBLK192, 256, CONV_SMEM>>>(
        T16a, WtH + (size_t)2 * 27 * 4096, T2a,
        T16b, WtH + (size_t)5 * 27 * 4096, T2b, nbr);

    // merged up: unit2 -> Ah, unit5 -> Bh (fp16 residual)
    k_lin<64, 128, 1, 1><<<2 * NBLK96, 256, SM_UP>>>(
        nullptr, T2a, V2H + (size_t)2 * 8192, V2L + (size_t)2 * 8192,
        Ah, nullptr, nullptr, nullptr, Ah,
        nullptr, T2b, V2H + (size_t)5 * 8192, V2L + (size_t)5 * 8192,
        Bh, nullptr, nullptr, nullptr, Bh);

    // final: out = Ah * sigmoid(Bh @ Wf) + x
    k_lin<128, 128, 2, 1><<<NBLK96, 256, SM_FINAL>>>(
        nullptr, Bh, VfH, VfL, Ah, nullptr, x, out, nullptr,
        nullptr, Bh, VfH, VfL, Ah, nullptr, x, out, nullptr);
}

// round 16
// speedup vs baseline: 1.2238x; 1.2238x over previous
#include <cuda_runtime.h>
#include <cuda_bf16.h>
#include <cuda_fp16.h>
#include <cstdint>

#define NPTS 120000
#define NBLK96 1250   // 120000 / 96 exactly
#define NBLK192 625   // 120000 / 192 exactly

// ---------------- scratch (device globals: allocation-free) ----------------
__device__ float g_A[NPTS * 128];
__device__ float g_B[NPTS * 128];
__device__ __half g_T2a[NPTS * 64];                 // conv output (fp16), branch a
__device__ __half g_T2b[NPTS * 64];                 // branch b
__device__ __half g_T16a[NPTS * 64];                // conv input (fp16), branch a
__device__ __half g_T16b[NPTS * 64];                // branch b
__device__ __half g_WtH[6 * 27 * 64 * 64];          // conv weights [u][k][j][c] fp16
__device__ __half g_V1H[6 * 64 * 128];              // down weights [u][n][k] fp16 hi/lo
__device__ __half g_V1L[6 * 64 * 128];
__device__ __half g_V1cH[128 * 128];                // concat down weights units 0|3
__device__ __half g_V1cL[128 * 128];
__device__ __half g_V2H[6 * 128 * 64];              // up weights [u][n][k] fp16 hi/lo
__device__ __half g_V2L[6 * 128 * 64];
__device__ __half g_VfH[128 * 128];                 // final weights [n][k] fp16 hi/lo
__device__ __half g_VfL[128 * 128];

// ---------------- helpers ---------------------------------------------------
__device__ __forceinline__ uint32_t smem_u32(const void* p) {
    uint32_t a;
    asm("{ .reg .u64 t; cvta.to.shared.u64 t, %1; cvt.u32.u64 %0, t; }"
        : "=r"(a) : "l"(p));
    return a;
}
__device__ __forceinline__ void ldsm_x4(uint32_t (&r)[4], uint32_t addr) {
    asm volatile("ldmatrix.sync.aligned.m8n8.x4.shared.b16 {%0,%1,%2,%3}, [%4];"
                 : "=r"(r[0]), "=r"(r[1]), "=r"(r[2]), "=r"(r[3]) : "r"(addr));
}
__device__ __forceinline__ void ldsm_x2(uint32_t (&r)[2], uint32_t addr) {
    asm volatile("ldmatrix.sync.aligned.m8n8.x2.shared.b16 {%0,%1}, [%2];"
                 : "=r"(r[0]), "=r"(r[1]) : "r"(addr));
}
__device__ __forceinline__ void mma_f16(float* c, const uint32_t* a,
                                        uint32_t b0, uint32_t b1) {
    asm volatile(
        "mma.sync.aligned.m16n8k16.row.col.f32.f16.f16.f32 "
        "{%0,%1,%2,%3}, {%4,%5,%6,%7}, {%8,%9}, {%0,%1,%2,%3};"
        : "+f"(c[0]), "+f"(c[1]), "+f"(c[2]), "+f"(c[3])
        : "r"(a[0]), "r"(a[1]), "r"(a[2]), "r"(a[3]), "r"(b0), "r"(b1));
}
__device__ __forceinline__ void cp_async16(uint32_t dst, const void* src,
                                           uint32_t src_size) {
    asm volatile("cp.async.ca.shared.global [%0], [%1], 16, %2;"
                 :: "r"(dst), "l"(src), "r"(src_size) : "memory");
}
__device__ __forceinline__ void cp_commit() {
    asm volatile("cp.async.commit_group;" ::: "memory");
}
template <int N>
__device__ __forceinline__ void cp_wait() {
    asm volatile("cp.async.wait_group %0;" :: "n"(N) : "memory");
}
__device__ __forceinline__ unsigned h2u(__half2 h) {
    return *reinterpret_cast<unsigned*>(&h);
}

// ---------------------------------------------------------------------------
// conv weight transpose: Wt[u][k][j][c] = Wk[u][k][c][j] as single fp16
// ---------------------------------------------------------------------------
__global__ void k_wsplit(const float* __restrict__ Wks,
                         __half* __restrict__ WtH) {
    int k = blockIdx.x, u = blockIdx.y;
    const float* src = Wks + ((size_t)u * 27 + k) * 4096;
    __half* dh = WtH + ((size_t)u * 27 + k) * 4096;
    for (int e = threadIdx.x; e < 4096; e += blockDim.x) {
        int c = e >> 6, j = e & 63;
        dh[j * 64 + c] = __float2half(src[c * 64 + j]);
    }
}

// ---------------------------------------------------------------------------
// linear weight split+transpose: [k][n] fp32 -> [n][k] fp16 hi/lo
// blocks 0-5: W1 units; 6-11: W2 units; 12: Wf; 13: concat W1 units 0|3
// ---------------------------------------------------------------------------
__global__ void k_wsplit_lin(const float* __restrict__ W1s,
                             const float* __restrict__ W2s,
                             const float* __restrict__ Wf,
                             __half* __restrict__ V1H, __half* __restrict__ V1L,
                             __half* __restrict__ V1cH, __half* __restrict__ V1cL,
                             __half* __restrict__ V2H, __half* __restrict__ V2L,
                             __half* __restrict__ VfH, __half* __restrict__ VfL) {
    int b = blockIdx.x;
    if (b < 6) {
        const float* s = W1s + (size_t)b * 8192;
        __half* vh = V1H + (size_t)b * 8192;
        __half* vl = V1L + (size_t)b * 8192;
        for (int e = threadIdx.x; e < 8192; e += blockDim.x) {
            int k = e >> 6, n = e & 63;
            float v = s[e];
            __half fh = __float2half(v);
            vh[n * 128 + k] = fh;
            vl[n * 128 + k] = __float2half(v - __half2float(fh));
        }
    } else if (b < 12) {
        const float* s = W2s + (size_t)(b - 6) * 8192;
        __half* vh = V2H + (size_t)(b - 6) * 8192;
        __half* vl = V2L + (size_t)(b - 6) * 8192;
        for (int e = threadIdx.x; e < 8192; e += blockDim.x) {
            int k = e >> 7, n = e & 127;
            float v = s[e];
            __half fh = __float2half(v);
            vh[n * 64 + k] = fh;
            vl[n * 64 + k] = __float2half(v - __half2float(fh));
        }
    } else if (b == 12) {
        for (int e = threadIdx.x; e < 16384; e += blockDim.x) {
            int k = e >> 7, n = e & 127;
            float v = Wf[e];
            __half fh = __float2half(v);
            VfH[n * 128 + k] = fh;
            VfL[n * 128 + k] = __float2half(v - __half2float(fh));
        }
    } else {
        // concat: out rows 0-63 = unit0, rows 64-127 = unit3
        for (int e = threadIdx.x; e < 16384; e += blockDim.x) {
            int k = e >> 7, n = e & 127;
            int u = (n < 64) ? 0 : 3;
            float v = W1s[(size_t)u * 8192 + k * 64 + (n & 63)];
            __half fh = __float2half(v);
            V1cH[n * 128 + k] = fh;
            V1cL[n * 128 + k] = __float2half(v - __half2float(fh));
        }
    }
}

// ---------------------------------------------------------------------------
// HMMA 1x1 layer, M=96 tiles, fp16 2-product, DUAL-BRANCH (R13-proven):
// EPI 1: in16 fp16 -> relu(acc+res) -> fp32 (stride 128)         [up]
// EPI 2: in fp32 -> res*sigmoid(acc)+xres -> fp32 (stride 128)   [final]
// EPI 3: in fp32 -> relu -> fp16, cols 0-63 -> out16_a, 64-127 -> out16_b
//        (single-branch grid NBLK96)                             [concat down]
// ---------------------------------------------------------------------------
template <int K, int N, int EPI>
__global__ __launch_bounds__(256, 2) void k_lin(
    const float* in_a, const __half* in16_a,
    const __half* BHa, const __half* BLa,
    const float* res_a, const float* xres_a,
    float* fout_a, __half* out16_a,
    const float* in_b, const __half* in16_b,
    const __half* BHb, const __half* BLb,
    const float* res_b, const float* xres_b,
    float* fout_b, __half* out16_b)
{
    constexpr int SB   = K * 2 + 16;
    constexpr int BOFF = 96 * SB;
    constexpr int NTW  = N / 4;
    constexpr int NT   = NTW / 8;
    constexpr int KS   = K / 16;

    extern __shared__ char sm[];
    const uint32_t su = smem_u32(sm);
    const int tid  = threadIdx.x;
    const int lane = tid & 31;
    const int w    = tid >> 5;
    const int wm   = w & 1;
    const int wn   = w >> 1;
    const int mbase = wm * 48;

    const int bid = blockIdx.x;
    const bool sel = bid >= NBLK96;
    const int p0 = (sel ? bid - NBLK96 : bid) * 96;
    const float*  in    = sel ? in_b    : in_a;
    const __half* in16  = sel ? in16_b  : in16_a;
    const __half* BH    = sel ? BHb     : BHa;
    const __half* BL    = sel ? BLb     : BLa;
    const float*  res   = sel ? res_b   : res_a;
    const float*  xres  = sel ? xres_b  : xres_a;
    float*        fout  = sel ? fout_b  : fout_a;
    __half*       out16 = sel ? out16_b : out16_a;

    // ---- stage A ----
    if (EPI == 1) {
        constexpr int CH = 96 * K / 8;
#pragma unroll
        for (int i = 0; i < CH / 256; i++) {
            int j = tid + i * 256;
            int row = j / (K / 8), ch = j % (K / 8);
            *(uint4*)(sm + row * SB + ch * 16) =
                *(const uint4*)(in16 + (size_t)(p0 + row) * K + ch * 8);
        }
    } else {
        constexpr int UNITS = 96 * K / 8;
#pragma unroll
        for (int i = 0; i < UNITS / 256; i++) {
            int j = tid + i * 256;
            int row = j / (K / 8), q = j % (K / 8);
            const float* src = in + (size_t)(p0 + row) * K + q * 8;
            float4 f0 = *(const float4*)(src);
            float4 f1 = *(const float4*)(src + 4);
            *(uint4*)(sm + row * SB + q * 16) = make_uint4(
                h2u(__floats2half2_rn(f0.x, f0.y)),
                h2u(__floats2half2_rn(f0.z, f0.w)),
                h2u(__floats2half2_rn(f1.x, f1.y)),
                h2u(__floats2half2_rn(f1.z, f1.w)));
        }
    }
    // ---- stage B (fp16 hi/lo) ----
    {
        constexpr int ITER = N * K / 1024;
        int plane = tid >> 7, t = tid & 127;
        const __half* bs = plane ? BL : BH;
        char* bd = sm + BOFF + plane * (N * SB);
#pragma unroll
        for (int i = 0; i < ITER; i++) {
            int j = t + i * 128;
            int e = j * 8;
            int r = e / K, c = e % K;
            *(uint4*)(bd + r * SB + c * 2) = *(const uint4*)(bs + e);
        }
    }
    __syncthreads();

    float acc[3][NT][4];
#pragma unroll
    for (int mt = 0; mt < 3; mt++)
#pragma unroll
        for (int nt = 0; nt < NT; nt++)
#pragma unroll
            for (int e = 0; e < 4; e++) acc[mt][nt][e] = 0.f;

    const uint32_t a_ld = su + (uint32_t)(mbase + (lane & 15)) * SB
                        + (uint32_t)(lane >> 4) * 16;
    const uint32_t b_ld = su + BOFF + (uint32_t)(wn * NTW + (lane & 7)) * SB
                        + (uint32_t)((lane >> 3) & 1) * 16;

#pragma unroll
    for (int ks = 0; ks < KS; ks++) {
        uint32_t a[3][4];
#pragma unroll
        for (int mt = 0; mt < 3; mt++)
            ldsm_x4(a[mt], a_ld + (uint32_t)mt * (16 * SB) + ks * 32);
#pragma unroll
        for (int nt = 0; nt < NT; nt++) {
            uint32_t bh[2], bl[2];
            ldsm_x2(bh, b_ld + (uint32_t)nt * (8 * SB) + ks * 32);
            ldsm_x2(bl, b_ld + (uint32_t)(N * SB) + (uint32_t)nt * (8 * SB) + ks * 32);
#pragma unroll
            for (int mt = 0; mt < 3; mt++) {
                mma_f16(acc[mt][nt], a[mt], bh[0], bh[1]);
                mma_f16(acc[mt][nt], a[mt], bl[0], bl[1]);
            }
        }
    }

    const int g = lane >> 2, tg = lane & 3;
#pragma unroll
    for (int mt = 0; mt < 3; mt++) {
        int r0 = p0 + mbase + mt * 16 + g;
#pragma unroll
        for (int nt = 0; nt < NT; nt++) {
            int col = wn * NTW + nt * 8 + tg * 2;
            float c0 = acc[mt][nt][0], c1 = acc[mt][nt][1];
            float c2 = acc[mt][nt][2], c3 = acc[mt][nt][3];
            if (EPI == 3) {
                __half* d0 = (col < 64) ? out16_a : out16_b;
                int cc = col & 63;
                *(__half2*)(d0 + (size_t)r0 * 64 + cc) =
                    __floats2half2_rn(fmaxf(c0, 0.f), fmaxf(c1, 0.f));
                *(__half2*)(d0 + (size_t)(r0 + 8) * 64 + cc) =
                    __floats2half2_rn(fmaxf(c2, 0.f), fmaxf(c3, 0.f));
            } else if (EPI == 1) {
                float2 ra = *(const float2*)(res + (size_t)r0 * 128 + col);
                float2 rb = *(const float2*)(res + (size_t)(r0 + 8) * 128 + col);
                float2 o0, o1;
                o0.x = fmaxf(c0 + ra.x, 0.f); o0.y = fmaxf(c1 + ra.y, 0.f);
                o1.x = fmaxf(c2 + rb.x, 0.f); o1.y = fmaxf(c3 + rb.y, 0.f);
                *(float2*)(fout + (size_t)r0 * 128 + col) = o0;
                *(float2*)(fout + (size_t)(r0 + 8) * 128 + col) = o1;
            } else {  // EPI == 2
                float2 aa = *(const float2*)(res  + (size_t)r0 * 128 + col);
                float2 xa = *(const float2*)(xres + (size_t)r0 * 128 + col);
                float2 ab = *(const float2*)(res  + (size_t)(r0 + 8) * 128 + col);
                float2 xb = *(const float2*)(xres + (size_t)(r0 + 8) * 128 + col);
                float2 o0, o1;
                o0.x = aa.x / (1.f + __expf(-c0)) + xa.x;
                o0.y = aa.y / (1.f + __expf(-c1)) + xa.y;
                o1.x = ab.x / (1.f + __expf(-c2)) + xb.x;
                o1.y = ab.y / (1.f + __expf(-c3)) + xb.y;
                *(float2*)(fout + (size_t)r0 * 128 + col) = o0;
                *(float2*)(fout + (size_t)(r0 + 8) * 128 + col) = o1;
            }
        }
    }
}

// ---------------------------------------------------------------------------
// FUSED up_i + down_{i+1}, M=96, fp16 2-product, DUAL-BRANCH (R13-proven)
// ---------------------------------------------------------------------------
#define UD_SB1 144
#define UD_B1 26112
#define UD_SB2 272
#define UD_B2 62976
#define UD_SMEM 97792

__global__ __launch_bounds__(256, 2) void k_updown(
    const __half* t2_a, const __half* W2Ha, const __half* W2La,
    const float* res_a, float* fout_a,
    const __half* V1Ha, const __half* V1La, __half* out16_a,
    const __half* t2_b, const __half* W2Hb, const __half* W2Lb,
    const float* res_b, float* fout_b,
    const __half* V1Hb, const __half* V1Lb, __half* out16_b)
{
    extern __shared__ char sm[];
    const uint32_t su = smem_u32(sm);
    const int tid  = threadIdx.x;
    const int lane = tid & 31;
    const int w    = tid >> 5;
    const int wm   = w & 1;
    const int wn   = w >> 1;
    const int mbase = wm * 48;

    const int bid = blockIdx.x;
    const bool sel = bid >= NBLK96;
    const int p0 = (sel ? bid - NBLK96 : bid) * 96;
    const __half* t2h   = sel ? t2_b    : t2_a;
    const __half* W2Hp  = sel ? W2Hb    : W2Ha;
    const __half* W2Lp  = sel ? W2Lb    : W2La;
    const float*  res   = sel ? res_b   : res_a;
    float*        fout  = sel ? fout_b  : fout_a;
    const __half* V1Hp  = sel ? V1Hb    : V1Ha;
    const __half* V1Lp  = sel ? V1Lb    : V1La;
    __half*       out16 = sel ? out16_b : out16_a;

#pragma unroll
    for (int i = 0; i < 3; i++) {
        int j = tid + i * 256;
        int row = j >> 3, ch = j & 7;
        *(uint4*)(sm + row * UD_SB1 + ch * 16) =
            *(const uint4*)(t2h + (size_t)(p0 + row) * 64 + ch * 8);
    }
    {
        int plane = tid >> 7, t = tid & 127;
        const __half* bs = plane ? W2Lp : W2Hp;
        char* bd = sm + UD_B1 + plane * 18432;
#pragma unroll
        for (int i = 0; i < 8; i++) {
            int j = t + i * 128;
            int e = j * 8;
            int r = e >> 6, c = e & 63;
            *(uint4*)(bd + r * UD_SB1 + c * 2) = *(const uint4*)(bs + e);
        }
    }
    {
        int plane = tid >> 7, t = tid & 127;
        const __half* bs = plane ? V1Lp : V1Hp;
        char* bd = sm + UD_B2 + plane * 17408;
#pragma unroll
        for (int i = 0; i < 8; i++) {
            int j = t + i * 128;
            int e = j * 8;
            int r = e >> 7, c = e & 127;
            *(uint4*)(bd + r * UD_SB2 + c * 2) = *(const uint4*)(bs + e);
        }
    }
    __syncthreads();

    float acc[3][4][4];
#pragma unroll
    for (int mt = 0; mt < 3; mt++)
#pragma unroll
        for (int nt = 0; nt < 4; nt++)
#pragma unroll
            for (int e = 0; e < 4; e++) acc[mt][nt][e] = 0.f;

    {
        const uint32_t a_ld = su + (uint32_t)(mbase + (lane & 15)) * UD_SB1
                            + (uint32_t)(lane >> 4) * 16;
        const uint32_t b_ld = su + UD_B1 + (uint32_t)(wn * 32 + (lane & 7)) * UD_SB1
                            + (uint32_t)((lane >> 3) & 1) * 16;
#pragma unroll
        for (int ks = 0; ks < 4; ks++) {
            uint32_t a[3][4];
#pragma unroll
            for (int mt = 0; mt < 3; mt++)
                ldsm_x4(a[mt], a_ld + (uint32_t)mt * (16 * UD_SB1) + ks * 32);
#pragma unroll
            for (int nt = 0; nt < 4; nt++) {
                uint32_t bh[2], bl[2];
                ldsm_x2(bh, b_ld + (uint32_t)nt * (8 * UD_SB1) + ks * 32);
                ldsm_x2(bl, b_ld + 18432u + (uint32_t)nt * (8 * UD_SB1) + ks * 32);
#pragma unroll
                for (int mt = 0; mt < 3; mt++) {
                    mma_f16(acc[mt][nt], a[mt], bh[0], bh[1]);
                    mma_f16(acc[mt][nt], a[mt], bl[0], bl[1]);
                }
            }
        }
    }
    __syncthreads();

    const int g = lane >> 2, tg = lane & 3;
#pragma unroll
    for (int mt = 0; mt < 3; mt++) {
        int lr0 = mbase + mt * 16 + g;
        int r0 = p0 + lr0;
#pragma unroll
        for (int nt = 0; nt < 4; nt++) {
            int col = wn * 32 + nt * 8 + tg * 2;
            float2 ra = *(const float2*)(res + (size_t)r0 * 128 + col);
            float2 rb = *(const float2*)(res + (size_t)(r0 + 8) * 128 + col);
            float2 o0, o1;
            o0.x = fmaxf(acc[mt][nt][0] + ra.x, 0.f);
            o0.y = fmaxf(acc[mt][nt][1] + ra.y, 0.f);
            o1.x = fmaxf(acc[mt][nt][2] + rb.x, 0.f);
            o1.y = fmaxf(acc[mt][nt][3] + rb.y, 0.f);
            *(float2*)(fout + (size_t)r0 * 128 + col) = o0;
            *(float2*)(fout + (size_t)(r0 + 8) * 128 + col) = o1;
            *(__half2*)(sm + lr0 * UD_SB2 + col * 2) = __floats2half2_rn(o0.x, o0.y);
            *(__half2*)(sm + (lr0 + 8) * UD_SB2 + col * 2) = __floats2half2_rn(o1.x, o1.y);
        }
    }
    __syncthreads();

    float acc2[3][2][4];
#pragma unroll
    for (int mt = 0; mt < 3; mt++)
#pragma unroll
        for (int nt = 0; nt < 2; nt++)
#pragma unroll
            for (int e = 0; e < 4; e++) acc2[mt][nt][e] = 0.f;

    {
        const uint32_t a_ld = su + (uint32_t)(mbase + (lane & 15)) * UD_SB2
                            + (uint32_t)(lane >> 4) * 16;
        const uint32_t b_ld = su + UD_B2 + (uint32_t)(wn * 16 + (lane & 7)) * UD_SB2
                            + (uint32_t)((lane >> 3) & 1) * 16;
#pragma unroll
        for (int ks = 0; ks < 8; ks++) {
            uint32_t a[3][4];
#pragma unroll
            for (int mt = 0; mt < 3; mt++)
                ldsm_x4(a[mt], a_ld + (uint32_t)mt * (16 * UD_SB2) + ks * 32);
#pragma unroll
            for (int nt = 0; nt < 2; nt++) {
                uint32_t bh[2], bl[2];
                ldsm_x2(bh, b_ld + (uint32_t)nt * (8 * UD_SB2) + ks * 32);
                ldsm_x2(bl, b_ld + 17408u + (uint32_t)nt * (8 * UD_SB2) + ks * 32);
#pragma unroll
                for (int mt = 0; mt < 3; mt++) {
                    mma_f16(acc2[mt][nt], a[mt], bh[0], bh[1]);
                    mma_f16(acc2[mt][nt], a[mt], bl[0], bl[1]);
                }
            }
        }
    }

#pragma unroll
    for (int mt = 0; mt < 3; mt++) {
        int r0 = p0 + mbase + mt * 16 + g;
#pragma unroll
        for (int nt = 0; nt < 2; nt++) {
            int col = wn * 16 + nt * 8 + tg * 2;
            __half2 o0 = __floats2half2_rn(fmaxf(acc2[mt][nt][0], 0.f),
                                           fmaxf(acc2[mt][nt][1], 0.f));
            __half2 o1 = __floats2half2_rn(fmaxf(acc2[mt][nt][2], 0.f),
                                           fmaxf(acc2[mt][nt][3], 0.f));
            *(__half2*)(out16 + (size_t)r0 * 64 + col) = o0;
            *(__half2*)(out16 + (size_t)(r0 + 8) * 64 + col) = o1;
        }
    }
}

// ---------------------------------------------------------------------------
// fp16 HMMA conv, DUAL-BRANCH, 2-stage cp.async, smem idx (R13-proven)
// ---------------------------------------------------------------------------
#define ASTRIDE 144
#define STAGE_SZ 36864
#define SB_B 27648
#define IDX_OFF 73728
#define CONV_SMEM (IDX_OFF + 20736)

__global__ __launch_bounds__(256, 2) void k_conv_mma(
    const __half* T16a, const __half* Wta, __half* outa,
    const __half* T16b, const __half* Wtb, __half* outb,
    const int* __restrict__ nbr)
{
    extern __shared__ char sm[];
    const int tid  = threadIdx.x;
    const int lane = tid & 31;
    const int w    = tid >> 5;
    const int wm   = w & 3;
    const int wn   = w >> 2;

    const int bid = blockIdx.x;
    const bool selb = bid >= NBLK192;
    const int p0 = (selb ? bid - NBLK192 : bid) * 192;
    const __half* T16  = selb ? T16b : T16a;
    const __half* WtH  = selb ? Wtb  : Wta;
    __half*       outh = selb ? outb : outa;

    const uint32_t su = smem_u32(sm);
    int* idxs = (int*)(sm + IDX_OFF);

    for (int i = tid; i < 27 * 192; i += 256) {
        int p = i / 27;
        int k = i - p * 27;
        idxs[k * 192 + p] = nbr[(size_t)(p0 + p) * 27 + k];
    }

    float acc[3][4][4];
#pragma unroll
    for (int mt = 0; mt < 3; mt++)
#pragma unroll
        for (int nt = 0; nt < 4; nt++)
#pragma unroll
            for (int e = 0; e < 4; e++) acc[mt][nt][e] = 0.f;

    const uint32_t a_ld0 = su + (uint32_t)(wm * 48 + (lane & 15)) * ASTRIDE
                         + (uint32_t)(lane >> 4) * 16;
    const uint32_t b_ld0 = su + SB_B + (uint32_t)(wn * 32 + (lane & 15)) * ASTRIDE
                         + (uint32_t)(lane >> 4) * 16;

    __syncthreads();

    auto issue_tap = [&](int k, uint32_t sbase) {
#pragma unroll
        for (int i = 0; i < 6; i++) {
            int j = tid + i * 256;
            int row = j >> 3, ch = j & 7;
            int gr = idxs[k * 192 + row];
            uint32_t dst = sbase + (uint32_t)row * ASTRIDE + (uint32_t)ch * 16;
            const void* src = T16 + ((size_t)(gr < 0 ? 0 : gr) * 64 + ch * 8);
            cp_async16(dst, src, gr < 0 ? 0u : 16u);
        }
#pragma unroll
        for (int i = 0; i < 2; i++) {
            int j = tid + i * 256;
            int row = j >> 3, ch = j & 7;
            uint32_t dst = sbase + (uint32_t)SB_B
                         + (uint32_t)row * ASTRIDE + (uint32_t)ch * 16;
            const __half* src = WtH + ((size_t)k * 64 + row) * 64 + ch * 8;
            cp_async16(dst, src, 16u);
        }
        cp_commit();
    };

    issue_tap(0, su);
    issue_tap(1, su + STAGE_SZ);

    for (int k = 0; k < 27; k++) {
        const uint32_t sb = (uint32_t)(k & 1) * STAGE_SZ;
        if (k < 26) cp_wait<1>(); else cp_wait<0>();
        __syncthreads();

        const uint32_t a_ld = a_ld0 + sb;
        const uint32_t b_ld = b_ld0 + sb;
#pragma unroll
        for (int ks = 0; ks < 4; ks++) {
            uint32_t a[3][4];
#pragma unroll
            for (int mt = 0; mt < 3; mt++)
                ldsm_x4(a[mt], a_ld + (uint32_t)mt * (16 * ASTRIDE) + ks * 32);
#pragma unroll
            for (int nt2 = 0; nt2 < 2; nt2++) {
                uint32_t bh[4];
                ldsm_x4(bh, b_ld + (uint32_t)nt2 * (16 * ASTRIDE) + ks * 32);
#pragma unroll
                for (int mt = 0; mt < 3; mt++) {
                    mma_f16(acc[mt][nt2 * 2 + 0], a[mt], bh[0], bh[2]);
                    mma_f16(acc[mt][nt2 * 2 + 1], a[mt], bh[1], bh[3]);
                }
            }
        }

        if (k < 25) {
            __syncthreads();
            issue_tap(k + 2, su + sb);
        }
    }

    const int g = lane >> 2, tg = lane & 3;
#pragma unroll
    for (int mt = 0; mt < 3; mt++) {
        int row0 = p0 + wm * 48 + mt * 16 + g;
#pragma unroll
        for (int nt = 0; nt < 4; nt++) {
            int col = wn * 32 + nt * 8 + tg * 2;
            __half2 o0 = __floats2half2_rn(fmaxf(acc[mt][nt][0], 0.f),
                                           fmaxf(acc[mt][nt][1], 0.f));
            __half2 o1 = __floats2half2_rn(fmaxf(acc[mt][nt][2], 0.f),
                                           fmaxf(acc[mt][nt][3], 0.f));
            *(__half2*)(outh + (size_t)row0 * 64 + col) = o0;
            *(__half2*)(outh + (size_t)(row0 + 8) * 64 + col) = o1;
        }
    }
}

// ---------------------------------------------------------------------------
extern "C" void kernel_launch(void* const* d_in, const int* in_sizes, int n_in,
                              void* d_out, int out_size)
{
    const float* x   = (const float*)d_in[0];
    const float* W1s = (const float*)d_in[1];
    const float* Wks = (const float*)d_in[2];
    const float* W2s = (const float*)d_in[3];
    const float* Wf  = (const float*)d_in[4];
    const int*   nbr = (const int*)d_in[5];
    float* out = (float*)d_out;

    float *A, *B;
    __half *T2a, *T2b, *T16a, *T16b, *WtH;
    __half *V1H, *V1L, *V1cH, *V1cL, *V2H, *V2L, *VfH, *VfL;
    cudaGetSymbolAddress((void**)&A,    g_A);
    cudaGetSymbolAddress((void**)&B,    g_B);
    cudaGetSymbolAddress((void**)&T2a,  g_T2a);
    cudaGetSymbolAddress((void**)&T2b,  g_T2b);
    cudaGetSymbolAddress((void**)&T16a, g_T16a);
    cudaGetSymbolAddress((void**)&T16b, g_T16b);
    cudaGetSymbolAddress((void**)&WtH,  g_WtH);
    cudaGetSymbolAddress((void**)&V1H,  g_V1H);
    cudaGetSymbolAddress((void**)&V1L,  g_V1L);
    cudaGetSymbolAddress((void**)&V1cH, g_V1cH);
    cudaGetSymbolAddress((void**)&V1cL, g_V1cL);
    cudaGetSymbolAddress((void**)&V2H,  g_V2H);
    cudaGetSymbolAddress((void**)&V2L,  g_V2L);
    cudaGetSymbolAddress((void**)&VfH,  g_VfH);
    cudaGetSymbolAddress((void**)&VfL,  g_VfL);

    constexpr int SM_DOWN  = 96 * 272 + 2 * 128 * 272;   // 95744 (concat N=128)
    constexpr int SM_UP    = 96 * 144 + 2 * 128 * 144;   // 50688
    constexpr int SM_FINAL = 96 * 272 + 2 * 128 * 272;   // 95744

    cudaFuncSetAttribute(k_conv_mma, cudaFuncAttributeMaxDynamicSharedMemorySize,
                         CONV_SMEM);
    cudaFuncSetAttribute(k_updown, cudaFuncAttributeMaxDynamicSharedMemorySize,
                         UD_SMEM);
    cudaFuncSetAttribute((const void*)k_lin<128, 128, 3>,
                         cudaFuncAttributeMaxDynamicSharedMemorySize, SM_DOWN);
    cudaFuncSetAttribute((const void*)k_lin<64, 128, 1>,
                         cudaFuncAttributeMaxDynamicSharedMemorySize, SM_UP);
    cudaFuncSetAttribute((const void*)k_lin<128, 128, 2>,
                         cudaFuncAttributeMaxDynamicSharedMemorySize, SM_FINAL);

    k_wsplit<<<dim3(27, 6), 256>>>(Wks, WtH);
    k_wsplit_lin<<<14, 256>>>(W1s, W2s, Wf, V1H, V1L, V1cH, V1cL,
                              V2H, V2L, VfH, VfL);

    // concat down: x @ [W1_0 | W1_3] -> T16a (cols 0-63), T16b (cols 64-127)
    k_lin<128, 128, 3><<<NBLK96, 256, SM_DOWN>>>(
        x, nullptr, V1cH, V1cL, nullptr, nullptr, nullptr, T16a,
        x, nullptr, V1cH, V1cL, nullptr, nullptr, nullptr, T16b);

    // two merged conv+updown steps (R13 structure)
    for (int s = 0; s < 2; s++) {
        const float* hinA = (s == 0) ? x : A;
        const float* hinB = (s == 0) ? x : B;
        k_conv_mma<<<2 * NBLK192, 256, CONV_SMEM>>>(
            T16a, WtH + (size_t)s * 27 * 4096, T2a,
            T16b, WtH + (size_t)(s + 3) * 27 * 4096, T2b, nbr);
        k_updown<<<2 * NBLK96, 256, UD_SMEM>>>(
            T2a, V2H + (size_t)s * 8192, V2L + (size_t)s * 8192,
            hinA, A, V1H + (size_t)(s + 1) * 8192, V1L + (size_t)(s + 1) * 8192,
            T16a,
            T2b, V2H + (size_t)(s + 3) * 8192, V2L + (size_t)(s + 3) * 8192,
            hinB, B, V1H + (size_t)(s + 4) * 8192, V1L + (size_t)(s + 4) * 8192,
            T16b);
    }

    // last merged conv (units 2 and 5)
    k_conv_mma<<<2 * NBLK192, 256, CONV_SMEM>>>(
        T16a, WtH + (size_t)2 * 27 * 4096, T2a,
        T16b, WtH + (size_t)5 * 27 * 4096, T2b, nbr);

    // merged up: unit2 -> A, unit5 -> B
    k_lin<64, 128, 1><<<2 * NBLK96, 256, SM_UP>>>(
        nullptr, T2a, V2H + (size_t)2 * 8192, V2L + (size_t)2 * 8192,
        A, nullptr, A, nullptr,
        nullptr, T2b, V2H + (size_t)5 * 8192, V2L + (size_t)5 * 8192,
        B, nullptr, B, nullptr);

    // final (single branch)
    k_lin<128, 128, 2><<<NBLK96, 256, SM_FINAL>>>(
        B, nullptr, VfH, VfL, A, x, out, nullptr,
        B, nullptr, VfH, VfL, A, x, out, nullptr);
}